// round 3
// baseline (speedup 1.0000x reference)
#include <cuda_runtime.h>

#define NVOX 524288
#define VOXB 262144

__device__ float g_y[27 * NVOX];
__device__ float g_fea[8192 * 64];
__device__ float g_fea2[8192 * 128];
__device__ float g_q[8192 * 64];
__device__ float g_ga[65536];
__device__ float g_act[8192 * 1024];
__device__ float g_part[64 * 1024 * 2];
__device__ float g_abA[1024];
__device__ float g_abB[1024];
__device__ float g_cent[2 * 128 * 16];
__device__ float g_cent2[2 * 128 * 64];
__device__ float g_kT[2 * 64 * 128];
__device__ float g_v[2 * 128 * 64];
__device__ float g_newo[NVOX];

// K1: y[j][v] = sum_c x[v,c] * dwc_w[c,j]
__global__ void k_conv1A(const float* __restrict__ x, const float* __restrict__ dwc_w) {
    __shared__ float sw[96 * 27];
    for (int i = threadIdx.x; i < 96 * 27; i += 256) sw[i] = dwc_w[i];
    __syncthreads();
    int v0 = blockIdx.x * 512 + threadIdx.x;
    int v1 = v0 + 256;
    float acc0[27], acc1[27];
#pragma unroll
    for (int j = 0; j < 27; j++) { acc0[j] = 0.f; acc1[j] = 0.f; }
    const float* x0 = x + (size_t)v0 * 96;
    const float* x1 = x + (size_t)v1 * 96;
#pragma unroll 1
    for (int cc = 0; cc < 12; cc++) {
        float4 a0 = *(const float4*)(x0 + cc * 8);
        float4 a1 = *(const float4*)(x0 + cc * 8 + 4);
        float4 b0 = *(const float4*)(x1 + cc * 8);
        float4 b1 = *(const float4*)(x1 + cc * 8 + 4);
        float xa[8] = {a0.x,a0.y,a0.z,a0.w,a1.x,a1.y,a1.z,a1.w};
        float xb[8] = {b0.x,b0.y,b0.z,b0.w,b1.x,b1.y,b1.z,b1.w};
#pragma unroll
        for (int i = 0; i < 8; i++) {
            const float* wr = sw + (cc * 8 + i) * 27;
#pragma unroll
            for (int j = 0; j < 27; j++) {
                float w = wr[j];
                acc0[j] += xa[i] * w;
                acc1[j] += xb[i] * w;
            }
        }
    }
#pragma unroll
    for (int j = 0; j < 27; j++) {
        g_y[j * NVOX + v0] = acc0[j];
        g_y[j * NVOX + v1] = acc1[j];
    }
}

// K2: gather 27 shifted taps + bias -> fea (b,4096,64)
__global__ void k_conv1B(const float* __restrict__ dwc_b) {
    int t = blockIdx.x * 256 + threadIdx.x;
    int b = t >> 18;
    int vox = t & (VOXB - 1);
    int d = vox >> 12, h = (vox >> 6) & 63, w = vox & 63;
    float s = dwc_b[0];
#pragma unroll
    for (int kd = 0; kd < 3; kd++)
#pragma unroll
        for (int kh = 0; kh < 3; kh++)
#pragma unroll
            for (int kw = 0; kw < 3; kw++) {
                int dd = d + kd - 1, hh = h + kh - 1, ww = w + kw - 1;
                if ((unsigned)dd < 64u && (unsigned)hh < 64u && (unsigned)ww < 64u)
                    s += g_y[(kd * 9 + kh * 3 + kw) * NVOX + b * VOXB + (dd << 12) + (hh << 6) + ww];
            }
    int n = ((d >> 2) << 8) + ((h >> 2) << 4) + (w >> 2);
    int f = ((d & 3) << 4) + ((h & 3) << 2) + (w & 3);
    g_fea[((b << 12) + n) * 64 + f] = s;
}

// K3: fea2 = fea@W1+b1 (cols 0..127), q = fea@Wq+bq (cols 128..191)
__global__ void k_fea2q(const float* __restrict__ few, const float* __restrict__ feb,
                        const float* __restrict__ qw,  const float* __restrict__ qb) {
    __shared__ float As[64 * 64];
    int row0 = blockIdx.x * 64;
    for (int i = threadIdx.x; i < 4096; i += 256) As[i] = g_fea[row0 * 64 + i];
    __syncthreads();
    int tx = threadIdx.x & 15, ty = threadIdx.x >> 4;
    int c0 = tx * 12;
    float acc[4][12];
#pragma unroll
    for (int r = 0; r < 4; r++)
#pragma unroll
        for (int j = 0; j < 12; j++) acc[r][j] = 0.f;
#pragma unroll 4
    for (int k = 0; k < 64; k++) {
        float a[4];
#pragma unroll
        for (int r = 0; r < 4; r++) a[r] = As[(ty * 4 + r) * 64 + k];
#pragma unroll
        for (int j = 0; j < 12; j++) {
            int col = c0 + j;
            float w = (col < 128) ? __ldg(few + k * 128 + col) : __ldg(qw + k * 64 + col - 128);
#pragma unroll
            for (int r = 0; r < 4; r++) acc[r][j] += a[r] * w;
        }
    }
#pragma unroll
    for (int r = 0; r < 4; r++) {
        int row = row0 + ty * 4 + r;
#pragma unroll
        for (int j = 0; j < 12; j++) {
            int col = c0 + j;
            if (col < 128) g_fea2[row * 128 + col] = acc[r][j] + __ldg(feb + col);
            else           g_q[row * 64 + col - 128] = acc[r][j] + __ldg(qb + col - 128);
        }
    }
}

// K4: ga = sigmoid(fea2 @ fc_ga_w + b)
__global__ void k_ga(const float* __restrict__ gw, const float* __restrict__ gb) {
    int row = (blockIdx.x * 256 + threadIdx.x) >> 5;
    int lane = threadIdx.x & 31;
    const float* r = g_fea2 + row * 128;
    float v[4];
#pragma unroll
    for (int i = 0; i < 4; i++) v[i] = r[lane + 32 * i];
#pragma unroll
    for (int g = 0; g < 8; g++) {
        float dot = 0.f;
#pragma unroll
        for (int i = 0; i < 4; i++) dot += v[i] * __ldg(gw + (lane + 32 * i) * 8 + g);
#pragma unroll
        for (int off = 16; off > 0; off >>= 1) dot += __shfl_xor_sync(0xffffffffu, dot, off);
        if (lane == 0) g_ga[row * 8 + g] = 1.f / (1.f + __expf(-(dot + __ldg(gb + g))));
    }
}

// K5: act_raw = fea2[8192,128] @ cw[128,1024]
__global__ void k_cluster(const float* __restrict__ cw) {
    __shared__ float As[16][128];
    __shared__ float Bs[16][128];
    int bn = blockIdx.x, bm = blockIdx.y;
    int tid = threadIdx.x;
    int tx = tid & 15, ty = tid >> 4;
    float acc[8][8];
#pragma unroll
    for (int i = 0; i < 8; i++)
#pragma unroll
        for (int j = 0; j < 8; j++) acc[i][j] = 0.f;
    const float* Ag = g_fea2 + bm * 128 * 128;
    const float* Bg = cw + bn * 128;
    int ar = tid >> 2, ak = (tid & 3) * 4;
    int br = tid >> 5, bc = (tid & 31) * 4;
    for (int kc = 0; kc < 128; kc += 16) {
        float4 a0 = *(const float4*)(Ag + ar * 128 + kc + ak);
        float4 a1 = *(const float4*)(Ag + (ar + 64) * 128 + kc + ak);
        float4 b0 = *(const float4*)(Bg + (kc + br) * 1024 + bc);
        float4 b1 = *(const float4*)(Bg + (kc + br + 8) * 1024 + bc);
        __syncthreads();
        As[ak + 0][ar] = a0.x; As[ak + 1][ar] = a0.y; As[ak + 2][ar] = a0.z; As[ak + 3][ar] = a0.w;
        As[ak + 0][ar + 64] = a1.x; As[ak + 1][ar + 64] = a1.y; As[ak + 2][ar + 64] = a1.z; As[ak + 3][ar + 64] = a1.w;
        *(float4*)&Bs[br][bc] = b0;
        *(float4*)&Bs[br + 8][bc] = b1;
        __syncthreads();
#pragma unroll
        for (int kk = 0; kk < 16; kk++) {
            float a[8], bb[8];
            *(float4*)(a)     = *(const float4*)&As[kk][ty * 8];
            *(float4*)(a + 4) = *(const float4*)&As[kk][ty * 8 + 4];
            *(float4*)(bb)     = *(const float4*)&Bs[kk][tx * 8];
            *(float4*)(bb + 4) = *(const float4*)&Bs[kk][tx * 8 + 4];
#pragma unroll
            for (int i = 0; i < 8; i++)
#pragma unroll
                for (int j = 0; j < 8; j++) acc[i][j] += a[i] * bb[j];
        }
    }
#pragma unroll
    for (int i = 0; i < 8; i++) {
        int row = bm * 128 + ty * 8 + i;
        *(float4*)(g_act + (size_t)row * 1024 + bn * 128 + tx * 8)     = make_float4(acc[i][0], acc[i][1], acc[i][2], acc[i][3]);
        *(float4*)(g_act + (size_t)row * 1024 + bn * 128 + tx * 8 + 4) = make_float4(acc[i][4], acc[i][5], acc[i][6], acc[i][7]);
    }
}

// K6: per-column partial sums over 128-row stripes
__global__ void k_cstat() {
    int blk = blockIdx.x, tid = threadIdx.x;
    float s[4] = {0,0,0,0}, q[4] = {0,0,0,0};
    const float* base = g_act + (size_t)blk * 128 * 1024;
    for (int r = 0; r < 128; r++) {
#pragma unroll
        for (int k = 0; k < 4; k++) {
            float v = base[r * 1024 + tid + k * 256];
            s[k] += v; q[k] += v * v;
        }
    }
#pragma unroll
    for (int k = 0; k < 4; k++) {
        int col = tid + k * 256;
        g_part[(blk * 1024 + col) * 2]     = s[k];
        g_part[(blk * 1024 + col) * 2 + 1] = q[k];
    }
}

// K7: finalize BN affine, zero cent
__global__ void k_cfin(const float* __restrict__ abg, const float* __restrict__ abb) {
    int col = blockIdx.x * 256 + threadIdx.x;
    float s = 0.f, q = 0.f;
    for (int b = 0; b < 64; b++) {
        s += g_part[(b * 1024 + col) * 2];
        q += g_part[(b * 1024 + col) * 2 + 1];
    }
    float m = s * (1.f / 8192.f);
    float var = q * (1.f / 8192.f) - m * m;
    float A = rsqrtf(var + 1e-5f) * __ldg(abg + col);
    g_abA[col] = A;
    g_abB[col] = __ldg(abb + col) - m * A;
#pragma unroll
    for (int i = 0; i < 4; i++) g_cent[col + 1024 * i] = 0.f;
}

// K8: BN + softmax + ga -> cent[b,c,f] reduction
__global__ void k_smcent() {
    __shared__ float sc[2048];
    for (int i = threadIdx.x; i < 2048; i += 256) sc[i] = 0.f;
    __syncthreads();
    int blk = blockIdx.x;
    int b = blk >> 6, blkInB = blk & 63;
    int warp = threadIdx.x >> 5, lane = threadIdx.x & 31;
    float acc[4][16];
#pragma unroll
    for (int i = 0; i < 4; i++)
#pragma unroll
        for (int f = 0; f < 16; f++) acc[i][f] = 0.f;
    int nbase = blkInB * 512 + warp * 64;
    for (int rr = 0; rr < 64; rr++) {
        int n = nbase + rr;
        int patch = n >> 3, grp = n & 7;
        const float* arow = g_act + (size_t)(b * 4096 + patch) * 1024 + grp * 128;
        float v[4];
#pragma unroll
        for (int i = 0; i < 4; i++) {
            int c = lane + 32 * i;
            v[i] = arow[c] * g_abA[grp * 128 + c] + g_abB[grp * 128 + c];
        }
        float m = fmaxf(fmaxf(v[0], v[1]), fmaxf(v[2], v[3]));
#pragma unroll
        for (int off = 16; off > 0; off >>= 1) m = fmaxf(m, __shfl_xor_sync(0xffffffffu, m, off));
        float p[4], ssum = 0.f;
#pragma unroll
        for (int i = 0; i < 4; i++) { p[i] = __expf(v[i] - m); ssum += p[i]; }
#pragma unroll
        for (int off = 16; off > 0; off >>= 1) ssum += __shfl_xor_sync(0xffffffffu, ssum, off);
        float scale = g_ga[b * 32768 + n] / ssum;
#pragma unroll
        for (int i = 0; i < 4; i++) p[i] *= scale;
        const float* f2 = g_fea2 + (size_t)(b * 4096 + patch) * 128 + grp * 16;
        float fv = (lane < 16) ? f2[lane] : 0.f;
#pragma unroll
        for (int f = 0; f < 16; f++) {
            float fvf = __shfl_sync(0xffffffffu, fv, f);
#pragma unroll
            for (int i = 0; i < 4; i++) acc[i][f] += p[i] * fvf;
        }
    }
#pragma unroll
    for (int i = 0; i < 4; i++)
#pragma unroll
        for (int f = 0; f < 16; f++) atomicAdd(&sc[(lane + 32 * i) * 16 + f], acc[i][f]);
    __syncthreads();
    for (int i = threadIdx.x; i < 2048; i += 256) atomicAdd(&g_cent[b * 2048 + i], sc[i]);
}

// K9: cent2 = cent @ proj_w + proj_b
__global__ void k_proj(const float* __restrict__ pjw, const float* __restrict__ pjb) {
    int idx = blockIdx.x * 256 + threadIdx.x;
    int b = idx >> 13, rem = idx & 8191, c = rem >> 6, f = rem & 63;
    float s = __ldg(pjb + f);
    const float* cr = g_cent + b * 2048 + c * 16;
#pragma unroll
    for (int g = 0; g < 16; g++) s += cr[g] * __ldg(pjw + g * 64 + f);
    g_cent2[idx] = s;
}

// K10: per-c BN over (b,f) then kv = cent_bn @ kv_w + kv_b; store kT and v
__global__ void k_bnkv(const float* __restrict__ pg, const float* __restrict__ pb,
                       const float* __restrict__ kvw, const float* __restrict__ kvb) {
    __shared__ float rs[128], rq[128], scent[128];
    int c = blockIdx.x, t = threadIdx.x;
    int b = t >> 6, f = t & 63;
    float val = g_cent2[b * 8192 + c * 64 + f];
    rs[t] = val; rq[t] = val * val;
    __syncthreads();
    for (int s = 64; s > 0; s >>= 1) {
        if (t < s) { rs[t] += rs[t + s]; rq[t] += rq[t + s]; }
        __syncthreads();
    }
    float mean = rs[0] * (1.f / 128.f);
    float var  = rq[0] * (1.f / 128.f) - mean * mean;
    float A = rsqrtf(var + 1e-5f) * __ldg(pg + c);
    float B = __ldg(pb + c) - mean * A;
    scent[t] = val * A + B;
    __syncthreads();
    float a0 = __ldg(kvb + t), a1 = a0;
    for (int ff = 0; ff < 64; ff++) {
        float w = __ldg(kvw + ff * 128 + t);
        a0 += scent[ff] * w;
        a1 += scent[64 + ff] * w;
    }
    if (t < 64) {
        g_kT[t * 128 + c] = a0;
        g_kT[(64 + t) * 128 + c] = a1;
    } else {
        g_v[c * 64 + t - 64] = a0;
        g_v[8192 + c * 64 + t - 64] = a1;
    }
}

// K11: attention q.kT -> softmax -> .v -> scatter to voxel layout
__global__ void k_attn() {
    int warp = threadIdx.x >> 5, lane = threadIdx.x & 31;
    int n = blockIdx.x * 8 + warp;
    int b = n >> 12, patch = n & 4095;
    const float* qr = g_q + n * 64;
    float q0 = qr[lane], q1 = qr[lane + 32];
    float s[4] = {0,0,0,0};
    const float* kTb = g_kT + b * 8192;
#pragma unroll 8
    for (int f = 0; f < 32; f++) {
        float qf = __shfl_sync(0xffffffffu, q0, f);
        const float* kr = kTb + f * 128;
#pragma unroll
        for (int i = 0; i < 4; i++) s[i] += qf * kr[lane + 32 * i];
    }
#pragma unroll 8
    for (int f = 0; f < 32; f++) {
        float qf = __shfl_sync(0xffffffffu, q1, f);
        const float* kr = kTb + (f + 32) * 128;
#pragma unroll
        for (int i = 0; i < 4; i++) s[i] += qf * kr[lane + 32 * i];
    }
#pragma unroll
    for (int i = 0; i < 4; i++) s[i] *= 0.125f;
    float m = fmaxf(fmaxf(s[0], s[1]), fmaxf(s[2], s[3]));
#pragma unroll
    for (int off = 16; off > 0; off >>= 1) m = fmaxf(m, __shfl_xor_sync(0xffffffffu, m, off));
    float p[4], sum = 0.f;
#pragma unroll
    for (int i = 0; i < 4; i++) { p[i] = __expf(s[i] - m); sum += p[i]; }
#pragma unroll
    for (int off = 16; off > 0; off >>= 1) sum += __shfl_xor_sync(0xffffffffu, sum, off);
    float inv = 1.f / sum;
#pragma unroll
    for (int i = 0; i < 4; i++) p[i] *= inv;
    float of0 = 0.f, of1 = 0.f;
    const float* vb = g_v + b * 8192;
#pragma unroll 16
    for (int c = 0; c < 128; c++) {
        float pc = __shfl_sync(0xffffffffu, p[c >> 5], c & 31);
        of0 += pc * vb[c * 64 + lane];
        of1 += pc * vb[c * 64 + lane + 32];
    }
    int bd = patch >> 8, bh = (patch >> 4) & 15, bw = patch & 15;
    int f = lane;
    int d = bd * 4 + (f >> 4), h = bh * 4 + ((f >> 2) & 3), w = bw * 4 + (f & 3);
    g_newo[b * VOXB + (d << 12) + (h << 6) + w] = of0;
    f = lane + 32;
    d = bd * 4 + (f >> 4); h = bh * 4 + ((f >> 2) & 3); w = bw * 4 + (f & 3);
    g_newo[b * VOXB + (d << 12) + (h << 6) + w] = of1;
}

// K12: conv2 (1->96) + residual + bias, channel-last output
__global__ void k_conv2(const float* __restrict__ x, const float* __restrict__ upcw,
                        const float* __restrict__ upcb, float* __restrict__ out) {
    __shared__ float sw[96 * 27];
    for (int i = threadIdx.x; i < 96 * 27; i += 256) sw[i] = upcw[i];
    __syncthreads();
    int warp = threadIdx.x >> 5, lane = threadIdx.x & 31;
    int v0 = blockIdx.x * 16 + warp * 2;
    float nvA[27], nvB[27];
#pragma unroll
    for (int pair = 0; pair < 2; pair++) {
        int v = v0 + pair;
        int b = v >> 18, rem = v & (VOXB - 1);
        int d = rem >> 12, h = (rem >> 6) & 63, w = rem & 63;
        float* nv = pair ? nvB : nvA;
#pragma unroll
        for (int kd = 0; kd < 3; kd++)
#pragma unroll
            for (int kh = 0; kh < 3; kh++)
#pragma unroll
                for (int kw = 0; kw < 3; kw++) {
                    int dd = d + kd - 1, hh = h + kh - 1, ww = w + kw - 1;
                    int j = kd * 9 + kh * 3 + kw;
                    nv[j] = ((unsigned)dd < 64u && (unsigned)hh < 64u && (unsigned)ww < 64u)
                          ? g_newo[b * VOXB + (dd << 12) + (hh << 6) + ww] : 0.f;
                }
    }
#pragma unroll
    for (int c3 = 0; c3 < 3; c3++) {
        int c = lane + 32 * c3;
        float bias = __ldg(upcb + c);
        float aA = x[(size_t)v0 * 96 + c] + bias;
        float aB = x[(size_t)(v0 + 1) * 96 + c] + bias;
        const float* wr = sw + c * 27;
#pragma unroll
        for (int j = 0; j < 27; j++) {
            float w = wr[j];
            aA += nvA[j] * w;
            aB += nvB[j] * w;
        }
        out[(size_t)v0 * 96 + c] = aA;
        out[(size_t)(v0 + 1) * 96 + c] = aB;
    }
}

extern "C" void kernel_launch(void* const* d_in, const int* in_sizes, int n_in,
                              void* d_out, int out_size) {
    const float* x      = (const float*)d_in[0];
    const float* dwc_w  = (const float*)d_in[1];
    const float* dwc_b  = (const float*)d_in[2];
    const float* upc_w  = (const float*)d_in[3];
    const float* upc_b  = (const float*)d_in[4];
    const float* few    = (const float*)d_in[5];
    const float* feb    = (const float*)d_in[6];
    const float* gaw    = (const float*)d_in[7];
    const float* gab    = (const float*)d_in[8];
    const float* cw     = (const float*)d_in[9];
    const float* abg    = (const float*)d_in[10];
    const float* abb    = (const float*)d_in[11];
    const float* pjw    = (const float*)d_in[12];
    const float* pjb    = (const float*)d_in[13];
    const float* pbg    = (const float*)d_in[14];
    const float* pbb    = (const float*)d_in[15];
    const float* qw     = (const float*)d_in[16];
    const float* qb     = (const float*)d_in[17];
    const float* kvw    = (const float*)d_in[18];
    const float* kvb    = (const float*)d_in[19];
    float* out = (float*)d_out;

    k_conv1A<<<1024, 256>>>(x, dwc_w);
    k_conv1B<<<2048, 256>>>(dwc_b);
    k_fea2q<<<128, 256>>>(few, feb, qw, qb);
    k_ga<<<1024, 256>>>(gaw, gab);
    k_cluster<<<dim3(8, 64), 256>>>(cw);
    k_cstat<<<64, 256>>>();
    k_cfin<<<4, 256>>>(abg, abb);
    k_smcent<<<128, 256>>>();
    k_proj<<<64, 256>>>(pjw, pjb);
    k_bnkv<<<128, 128>>>(pbg, pbb, kvw, kvb);
    k_attn<<<1024, 256>>>();
    k_conv2<<<32768, 256>>>(x, upc_w, upc_b, out);
}

// round 4
// speedup vs baseline: 1.5194x; 1.5194x over previous
#include <cuda_runtime.h>
#include <cuda_bf16.h>

#define NVOX 524288
#define VOXB 262144

__device__ float g_y[27 * NVOX];
__device__ float g_fea[8192 * 64];
__device__ float g_fea2[8192 * 128];
__device__ float g_q[8192 * 64];
__device__ float g_ga[65536];
__device__ float g_act[8192 * 1024];
__device__ float g_part[64 * 1024 * 2];
__device__ float g_abA[1024];
__device__ float g_abB[1024];
__device__ float g_cent[2 * 128 * 16];
__device__ float g_cent2[2 * 128 * 64];
__device__ float g_kT[2 * 64 * 128];
__device__ float g_v[2 * 128 * 64];
__device__ float g_newo[NVOX];

__device__ __forceinline__ void mma_bf16(float c[4], const unsigned a[4], const unsigned b[2]) {
    asm volatile(
        "mma.sync.aligned.m16n8k16.row.col.f32.bf16.bf16.f32 "
        "{%0,%1,%2,%3}, {%4,%5,%6,%7}, {%8,%9}, {%0,%1,%2,%3};"
        : "+f"(c[0]), "+f"(c[1]), "+f"(c[2]), "+f"(c[3])
        : "r"(a[0]), "r"(a[1]), "r"(a[2]), "r"(a[3]), "r"(b[0]), "r"(b[1]));
}

__device__ __forceinline__ unsigned pack_bf16(float lo, float hi) {
    __nv_bfloat162 h = __floats2bfloat162_rn(lo, hi);
    return *(unsigned*)&h;
}

// ============ K1: conv1 stage A via bf16 MMA: y[j][v] = x[v,:96] @ W[:96,j] ======
// M-tile 128 voxels, N=32 (27 taps padded), K=96.
__global__ void k_conv1A(const float* __restrict__ x, const float* __restrict__ dwc_w) {
    const int SA = 104;
    __shared__ __nv_bfloat16 As[128 * 104];
    __shared__ __nv_bfloat16 Bs[32 * 104];
    int tid = threadIdx.x, w = tid >> 5, lane = tid & 31;
    int r = lane >> 2, qp = lane & 3;
    int v0 = blockIdx.x * 128;
    // A: x rows -> bf16 smem
    for (int i = tid; i < 128 * 48; i += 256) {
        int row = i / 48, p = i % 48;
        float2 f = *(const float2*)(x + (size_t)(v0 + row) * 96 + 2 * p);
        *(unsigned*)&As[row * SA + 2 * p] = pack_bf16(f.x, f.y);
    }
    // B: Bs[n=j][k=c] = W[c][j], taps 27..31 zero
    for (int i = tid; i < 32 * 96; i += 256) {
        int j = i / 96, c = i % 96;
        Bs[j * SA + c] = __float2bfloat16(j < 27 ? dwc_w[c * 27 + j] : 0.f);
    }
    __syncthreads();
    int wm = (w & 3) * 32, wn = (w >> 2) * 16;
    float c[2][2][4];
#pragma unroll
    for (int ms = 0; ms < 2; ms++)
#pragma unroll
        for (int ns = 0; ns < 2; ns++)
#pragma unroll
            for (int i = 0; i < 4; i++) c[ms][ns][i] = 0.f;
#pragma unroll
    for (int ks = 0; ks < 6; ks++) {
        int k0 = ks * 16 + 2 * qp;
        unsigned a[2][4], b[2][2];
#pragma unroll
        for (int ms = 0; ms < 2; ms++) {
            int row = wm + ms * 16 + r;
            a[ms][0] = *(unsigned*)&As[row * SA + k0];
            a[ms][1] = *(unsigned*)&As[(row + 8) * SA + k0];
            a[ms][2] = *(unsigned*)&As[row * SA + k0 + 8];
            a[ms][3] = *(unsigned*)&As[(row + 8) * SA + k0 + 8];
        }
#pragma unroll
        for (int ns = 0; ns < 2; ns++) {
            int n = wn + ns * 8 + r;
            b[ns][0] = *(unsigned*)&Bs[n * SA + k0];
            b[ns][1] = *(unsigned*)&Bs[n * SA + k0 + 8];
        }
#pragma unroll
        for (int ms = 0; ms < 2; ms++)
#pragma unroll
            for (int ns = 0; ns < 2; ns++) mma_bf16(c[ms][ns], a[ms], b[ns]);
    }
#pragma unroll
    for (int ms = 0; ms < 2; ms++)
#pragma unroll
        for (int ns = 0; ns < 2; ns++) {
            int v = v0 + wm + ms * 16 + r;
            int j0 = wn + ns * 8 + 2 * qp;
            if (j0 < 27) {
                g_y[j0 * NVOX + v] = c[ms][ns][0];
                g_y[j0 * NVOX + v + 8] = c[ms][ns][2];
            }
            if (j0 + 1 < 27) {
                g_y[(j0 + 1) * NVOX + v] = c[ms][ns][1];
                g_y[(j0 + 1) * NVOX + v + 8] = c[ms][ns][3];
            }
        }
}

// ============ K2: gather 27 shifted taps + bias -> fea (b,4096,64) ===============
__global__ void k_conv1B(const float* __restrict__ dwc_b) {
    int t = blockIdx.x * 256 + threadIdx.x;
    int b = t >> 18;
    int vox = t & (VOXB - 1);
    int d = vox >> 12, h = (vox >> 6) & 63, w = vox & 63;
    float s = dwc_b[0];
#pragma unroll
    for (int kd = 0; kd < 3; kd++)
#pragma unroll
        for (int kh = 0; kh < 3; kh++)
#pragma unroll
            for (int kw = 0; kw < 3; kw++) {
                int dd = d + kd - 1, hh = h + kh - 1, ww = w + kw - 1;
                if ((unsigned)dd < 64u && (unsigned)hh < 64u && (unsigned)ww < 64u)
                    s += g_y[(kd * 9 + kh * 3 + kw) * NVOX + b * VOXB + (dd << 12) + (hh << 6) + ww];
            }
    int n = ((d >> 2) << 8) + ((h >> 2) << 4) + (w >> 2);
    int f = ((d & 3) << 4) + ((h & 3) << 2) + (w & 3);
    g_fea[((b << 12) + n) * 64 + f] = s;
}

// ============ K3: fea2 = fea@W1+b1, q = fea@Wq+bq ================================
__global__ void k_fea2q(const float* __restrict__ few, const float* __restrict__ feb,
                        const float* __restrict__ qw,  const float* __restrict__ qb) {
    __shared__ float As[64 * 64];
    int row0 = blockIdx.x * 64;
    for (int i = threadIdx.x; i < 4096; i += 256) As[i] = g_fea[row0 * 64 + i];
    __syncthreads();
    int tx = threadIdx.x & 15, ty = threadIdx.x >> 4;
    int c0 = tx * 12;
    float acc[4][12];
#pragma unroll
    for (int r = 0; r < 4; r++)
#pragma unroll
        for (int j = 0; j < 12; j++) acc[r][j] = 0.f;
#pragma unroll 4
    for (int k = 0; k < 64; k++) {
        float a[4];
#pragma unroll
        for (int r = 0; r < 4; r++) a[r] = As[(ty * 4 + r) * 64 + k];
#pragma unroll
        for (int j = 0; j < 12; j++) {
            int col = c0 + j;
            float w = (col < 128) ? __ldg(few + k * 128 + col) : __ldg(qw + k * 64 + col - 128);
#pragma unroll
            for (int r = 0; r < 4; r++) acc[r][j] += a[r] * w;
        }
    }
#pragma unroll
    for (int r = 0; r < 4; r++) {
        int row = row0 + ty * 4 + r;
#pragma unroll
        for (int j = 0; j < 12; j++) {
            int col = c0 + j;
            if (col < 128) g_fea2[row * 128 + col] = acc[r][j] + __ldg(feb + col);
            else           g_q[row * 64 + col - 128] = acc[r][j] + __ldg(qb + col - 128);
        }
    }
}

// ============ K4: ga = sigmoid(fea2 @ fc_ga_w + b) ===============================
__global__ void k_ga(const float* __restrict__ gw, const float* __restrict__ gb) {
    int row = (blockIdx.x * 256 + threadIdx.x) >> 5;
    int lane = threadIdx.x & 31;
    const float* r = g_fea2 + row * 128;
    float v[4];
#pragma unroll
    for (int i = 0; i < 4; i++) v[i] = r[lane + 32 * i];
#pragma unroll
    for (int g = 0; g < 8; g++) {
        float dot = 0.f;
#pragma unroll
        for (int i = 0; i < 4; i++) dot += v[i] * __ldg(gw + (lane + 32 * i) * 8 + g);
#pragma unroll
        for (int off = 16; off > 0; off >>= 1) dot += __shfl_xor_sync(0xffffffffu, dot, off);
        if (lane == 0) g_ga[row * 8 + g] = 1.f / (1.f + __expf(-(dot + __ldg(gb + g))));
    }
}

// ============ K5: act = fea2[8192,128] @ cw[128,1024] via bf16 MMA ===============
// block tile 128x128, K chunks of 64.
__global__ void k_cluster(const float* __restrict__ cw) {
    const int SA = 72;
    __shared__ __nv_bfloat16 As[128 * 72];
    __shared__ __nv_bfloat16 Bs[128 * 72];
    int bn = blockIdx.x, bm = blockIdx.y;
    int tid = threadIdx.x, w = tid >> 5, lane = tid & 31;
    int r = lane >> 2, qp = lane & 3;
    int wm = (w & 3) * 32, wn = (w >> 2) * 64;
    float c[2][8][4];
#pragma unroll
    for (int ms = 0; ms < 2; ms++)
#pragma unroll
        for (int ns = 0; ns < 8; ns++)
#pragma unroll
            for (int i = 0; i < 4; i++) c[ms][ns][i] = 0.f;
    for (int kc = 0; kc < 128; kc += 64) {
        __syncthreads();
        for (int i = tid; i < 128 * 32; i += 256) {
            int row = i >> 5, p = i & 31;
            float2 f = *(const float2*)(g_fea2 + (bm * 128 + row) * 128 + kc + 2 * p);
            *(unsigned*)&As[row * SA + 2 * p] = pack_bf16(f.x, f.y);
        }
        for (int i = tid; i < 64 * 128; i += 256) {
            int k = i >> 7, n = i & 127;
            Bs[n * SA + k] = __float2bfloat16(cw[(kc + k) * 1024 + bn * 128 + n]);
        }
        __syncthreads();
#pragma unroll
        for (int ks = 0; ks < 4; ks++) {
            int k0 = ks * 16 + 2 * qp;
            unsigned a[2][4], b[8][2];
#pragma unroll
            for (int ms = 0; ms < 2; ms++) {
                int row = wm + ms * 16 + r;
                a[ms][0] = *(unsigned*)&As[row * SA + k0];
                a[ms][1] = *(unsigned*)&As[(row + 8) * SA + k0];
                a[ms][2] = *(unsigned*)&As[row * SA + k0 + 8];
                a[ms][3] = *(unsigned*)&As[(row + 8) * SA + k0 + 8];
            }
#pragma unroll
            for (int ns = 0; ns < 8; ns++) {
                int n = wn + ns * 8 + r;
                b[ns][0] = *(unsigned*)&Bs[n * SA + k0];
                b[ns][1] = *(unsigned*)&Bs[n * SA + k0 + 8];
            }
#pragma unroll
            for (int ms = 0; ms < 2; ms++)
#pragma unroll
                for (int ns = 0; ns < 8; ns++) mma_bf16(c[ms][ns], a[ms], b[ns]);
        }
    }
#pragma unroll
    for (int ms = 0; ms < 2; ms++)
#pragma unroll
        for (int ns = 0; ns < 8; ns++) {
            int row = bm * 128 + wm + ms * 16 + r;
            int col = bn * 128 + wn + ns * 8 + 2 * qp;
            *(float2*)(g_act + (size_t)row * 1024 + col) = make_float2(c[ms][ns][0], c[ms][ns][1]);
            *(float2*)(g_act + (size_t)(row + 8) * 1024 + col) = make_float2(c[ms][ns][2], c[ms][ns][3]);
        }
}

// ============ K6: per-column partial sums over 128-row stripes ===================
__global__ void k_cstat() {
    int blk = blockIdx.x, tid = threadIdx.x;
    float s[4] = {0,0,0,0}, q[4] = {0,0,0,0};
    const float* base = g_act + (size_t)blk * 128 * 1024;
    for (int r = 0; r < 128; r++) {
#pragma unroll
        for (int k = 0; k < 4; k++) {
            float v = base[r * 1024 + tid + k * 256];
            s[k] += v; q[k] += v * v;
        }
    }
#pragma unroll
    for (int k = 0; k < 4; k++) {
        int col = tid + k * 256;
        g_part[(blk * 1024 + col) * 2]     = s[k];
        g_part[(blk * 1024 + col) * 2 + 1] = q[k];
    }
}

// ============ K7: finalize BN affine, zero cent ==================================
__global__ void k_cfin(const float* __restrict__ abg, const float* __restrict__ abb) {
    int col = blockIdx.x * 256 + threadIdx.x;
    float s = 0.f, q = 0.f;
    for (int b = 0; b < 64; b++) {
        s += g_part[(b * 1024 + col) * 2];
        q += g_part[(b * 1024 + col) * 2 + 1];
    }
    float m = s * (1.f / 8192.f);
    float var = q * (1.f / 8192.f) - m * m;
    float A = rsqrtf(var + 1e-5f) * __ldg(abg + col);
    g_abA[col] = A;
    g_abB[col] = __ldg(abb + col) - m * A;
#pragma unroll
    for (int i = 0; i < 4; i++) g_cent[col + 1024 * i] = 0.f;
}

// ============ K8: BN + softmax + ga -> cent[b,c,f] reduction =====================
__global__ void k_smcent() {
    __shared__ float sc[2048];
    for (int i = threadIdx.x; i < 2048; i += 256) sc[i] = 0.f;
    __syncthreads();
    int blk = blockIdx.x;
    int b = blk >> 6, blkInB = blk & 63;
    int warp = threadIdx.x >> 5, lane = threadIdx.x & 31;
    float acc[4][16];
#pragma unroll
    for (int i = 0; i < 4; i++)
#pragma unroll
        for (int f = 0; f < 16; f++) acc[i][f] = 0.f;
    int nbase = blkInB * 512 + warp * 64;
    for (int rr = 0; rr < 64; rr++) {
        int n = nbase + rr;
        int patch = n >> 3, grp = n & 7;
        const float* arow = g_act + (size_t)(b * 4096 + patch) * 1024 + grp * 128;
        float v[4];
#pragma unroll
        for (int i = 0; i < 4; i++) {
            int c = lane + 32 * i;
            v[i] = arow[c] * g_abA[grp * 128 + c] + g_abB[grp * 128 + c];
        }
        float m = fmaxf(fmaxf(v[0], v[1]), fmaxf(v[2], v[3]));
#pragma unroll
        for (int off = 16; off > 0; off >>= 1) m = fmaxf(m, __shfl_xor_sync(0xffffffffu, m, off));
        float p[4], ssum = 0.f;
#pragma unroll
        for (int i = 0; i < 4; i++) { p[i] = __expf(v[i] - m); ssum += p[i]; }
#pragma unroll
        for (int off = 16; off > 0; off >>= 1) ssum += __shfl_xor_sync(0xffffffffu, ssum, off);
        float scale = g_ga[b * 32768 + n] / ssum;
#pragma unroll
        for (int i = 0; i < 4; i++) p[i] *= scale;
        const float* f2 = g_fea2 + (size_t)(b * 4096 + patch) * 128 + grp * 16;
        float fv = (lane < 16) ? f2[lane] : 0.f;
#pragma unroll
        for (int f = 0; f < 16; f++) {
            float fvf = __shfl_sync(0xffffffffu, fv, f);
#pragma unroll
            for (int i = 0; i < 4; i++) acc[i][f] += p[i] * fvf;
        }
    }
#pragma unroll
    for (int i = 0; i < 4; i++)
#pragma unroll
        for (int f = 0; f < 16; f++) atomicAdd(&sc[(lane + 32 * i) * 16 + f], acc[i][f]);
    __syncthreads();
    for (int i = threadIdx.x; i < 2048; i += 256) atomicAdd(&g_cent[b * 2048 + i], sc[i]);
}

// ============ K9: cent2 = cent @ proj_w + proj_b =================================
__global__ void k_proj(const float* __restrict__ pjw, const float* __restrict__ pjb) {
    int idx = blockIdx.x * 256 + threadIdx.x;
    int b = idx >> 13, rem = idx & 8191, c = rem >> 6, f = rem & 63;
    float s = __ldg(pjb + f);
    const float* cr = g_cent + b * 2048 + c * 16;
#pragma unroll
    for (int g = 0; g < 16; g++) s += cr[g] * __ldg(pjw + g * 64 + f);
    g_cent2[idx] = s;
}

// ============ K10: per-c BN then kv = cent_bn @ kv_w + kv_b ======================
__global__ void k_bnkv(const float* __restrict__ pg, const float* __restrict__ pb,
                       const float* __restrict__ kvw, const float* __restrict__ kvb) {
    __shared__ float rs[128], rq[128], scent[128];
    int c = blockIdx.x, t = threadIdx.x;
    int b = t >> 6, f = t & 63;
    float val = g_cent2[b * 8192 + c * 64 + f];
    rs[t] = val; rq[t] = val * val;
    __syncthreads();
    for (int s = 64; s > 0; s >>= 1) {
        if (t < s) { rs[t] += rs[t + s]; rq[t] += rq[t + s]; }
        __syncthreads();
    }
    float mean = rs[0] * (1.f / 128.f);
    float var  = rq[0] * (1.f / 128.f) - mean * mean;
    float A = rsqrtf(var + 1e-5f) * __ldg(pg + c);
    float B = __ldg(pb + c) - mean * A;
    scent[t] = val * A + B;
    __syncthreads();
    float a0 = __ldg(kvb + t), a1 = a0;
    for (int ff = 0; ff < 64; ff++) {
        float w = __ldg(kvw + ff * 128 + t);
        a0 += scent[ff] * w;
        a1 += scent[64 + ff] * w;
    }
    if (t < 64) {
        g_kT[t * 128 + c] = a0;
        g_kT[(64 + t) * 128 + c] = a1;
    } else {
        g_v[c * 64 + t - 64] = a0;
        g_v[8192 + c * 64 + t - 64] = a1;
    }
}

// ============ K11: attention =====================================================
__global__ void k_attn() {
    int warp = threadIdx.x >> 5, lane = threadIdx.x & 31;
    int n = blockIdx.x * 8 + warp;
    int b = n >> 12, patch = n & 4095;
    const float* qr = g_q + n * 64;
    float q0 = qr[lane], q1 = qr[lane + 32];
    float s[4] = {0,0,0,0};
    const float* kTb = g_kT + b * 8192;
#pragma unroll 8
    for (int f = 0; f < 32; f++) {
        float qf = __shfl_sync(0xffffffffu, q0, f);
        const float* kr = kTb + f * 128;
#pragma unroll
        for (int i = 0; i < 4; i++) s[i] += qf * kr[lane + 32 * i];
    }
#pragma unroll 8
    for (int f = 0; f < 32; f++) {
        float qf = __shfl_sync(0xffffffffu, q1, f);
        const float* kr = kTb + (f + 32) * 128;
#pragma unroll
        for (int i = 0; i < 4; i++) s[i] += qf * kr[lane + 32 * i];
    }
#pragma unroll
    for (int i = 0; i < 4; i++) s[i] *= 0.125f;
    float m = fmaxf(fmaxf(s[0], s[1]), fmaxf(s[2], s[3]));
#pragma unroll
    for (int off = 16; off > 0; off >>= 1) m = fmaxf(m, __shfl_xor_sync(0xffffffffu, m, off));
    float p[4], sum = 0.f;
#pragma unroll
    for (int i = 0; i < 4; i++) { p[i] = __expf(s[i] - m); sum += p[i]; }
#pragma unroll
    for (int off = 16; off > 0; off >>= 1) sum += __shfl_xor_sync(0xffffffffu, sum, off);
    float inv = 1.f / sum;
#pragma unroll
    for (int i = 0; i < 4; i++) p[i] *= inv;
    float of0 = 0.f, of1 = 0.f;
    const float* vb = g_v + b * 8192;
#pragma unroll 16
    for (int c = 0; c < 128; c++) {
        float pc = __shfl_sync(0xffffffffu, p[c >> 5], c & 31);
        of0 += pc * vb[c * 64 + lane];
        of1 += pc * vb[c * 64 + lane + 32];
    }
    int bd = patch >> 8, bh = (patch >> 4) & 15, bw = patch & 15;
    int f = lane;
    int d = bd * 4 + (f >> 4), h = bh * 4 + ((f >> 2) & 3), w = bw * 4 + (f & 3);
    g_newo[b * VOXB + (d << 12) + (h << 6) + w] = of0;
    f = lane + 32;
    d = bd * 4 + (f >> 4); h = bh * 4 + ((f >> 2) & 3); w = bw * 4 + (f & 3);
    g_newo[b * VOXB + (d << 12) + (h << 6) + w] = of1;
}

// ============ K12: conv2 (1->96) + residual via bf16 MMA =========================
// Block: 128 voxels = 2 h-rows x 64 w at fixed (b,d). A[128x32] taps, B[j][c].
__global__ void k_conv2(const float* __restrict__ x, const float* __restrict__ upcw,
                        const float* __restrict__ upcb, float* __restrict__ out) {
    const int SA = 40;
    __shared__ float halo[3 * 4 * 66];
    __shared__ __nv_bfloat16 As[128 * 40];
    __shared__ __nv_bfloat16 Bs[96 * 40];
    int tid = threadIdx.x, w = tid >> 5, lane = tid & 31;
    int r = lane >> 2, qp = lane & 3;
    int blk = blockIdx.x;
    int ht = blk & 31, d = (blk >> 5) & 63, b = blk >> 11;
    int h0 = ht * 2;
    int v0 = ((b * 64 + d) * 64 + h0) * 64;
    for (int i = tid; i < 792; i += 256) {
        int dd = i / 264, rem = i % 264, hh = rem / 66, ww = rem % 66;
        int gd = d - 1 + dd, gh = h0 - 1 + hh, gw = ww - 1;
        float val = 0.f;
        if ((unsigned)gd < 64u && (unsigned)gh < 64u && (unsigned)gw < 64u)
            val = g_newo[b * VOXB + (gd << 12) + (gh << 6) + gw];
        halo[i] = val;
    }
    for (int i = tid; i < 96 * 32; i += 256) {
        int c = i >> 5, j = i & 31;
        Bs[c * SA + j] = __float2bfloat16(j < 27 ? upcw[c * 27 + j] : 0.f);
    }
    __syncthreads();
    for (int i = tid; i < 128 * 32; i += 256) {
        int vox = i >> 5, j = i & 31;
        float val = 0.f;
        if (j < 27) {
            int kd = j / 9, kh = (j % 9) / 3, kw = j % 3;
            val = halo[(kd * 4 + (vox >> 6) + kh) * 66 + (vox & 63) + kw];
        }
        As[vox * SA + j] = __float2bfloat16(val);
    }
    __syncthreads();
    int wm = (w & 3) * 32, wn = (w >> 2) * 48;
    float c[2][6][4];
#pragma unroll
    for (int ms = 0; ms < 2; ms++)
#pragma unroll
        for (int ns = 0; ns < 6; ns++)
#pragma unroll
            for (int i = 0; i < 4; i++) c[ms][ns][i] = 0.f;
#pragma unroll
    for (int ks = 0; ks < 2; ks++) {
        int k0 = ks * 16 + 2 * qp;
        unsigned a[2][4], bfr[6][2];
#pragma unroll
        for (int ms = 0; ms < 2; ms++) {
            int row = wm + ms * 16 + r;
            a[ms][0] = *(unsigned*)&As[row * SA + k0];
            a[ms][1] = *(unsigned*)&As[(row + 8) * SA + k0];
            a[ms][2] = *(unsigned*)&As[row * SA + k0 + 8];
            a[ms][3] = *(unsigned*)&As[(row + 8) * SA + k0 + 8];
        }
#pragma unroll
        for (int ns = 0; ns < 6; ns++) {
            int n = wn + ns * 8 + r;
            bfr[ns][0] = *(unsigned*)&Bs[n * SA + k0];
            bfr[ns][1] = *(unsigned*)&Bs[n * SA + k0 + 8];
        }
#pragma unroll
        for (int ms = 0; ms < 2; ms++)
#pragma unroll
            for (int ns = 0; ns < 6; ns++) mma_bf16(c[ms][ns], a[ms], bfr[ns]);
    }
#pragma unroll
    for (int ms = 0; ms < 2; ms++)
#pragma unroll
        for (int ns = 0; ns < 6; ns++) {
            int vl = wm + ms * 16 + r;
            int col = wn + ns * 8 + 2 * qp;
            float b0 = __ldg(upcb + col), b1 = __ldg(upcb + col + 1);
            size_t base0 = (size_t)(v0 + vl) * 96 + col;
            size_t base1 = (size_t)(v0 + vl + 8) * 96 + col;
            float2 x0 = *(const float2*)(x + base0);
            float2 x1 = *(const float2*)(x + base1);
            *(float2*)(out + base0) = make_float2(c[ms][ns][0] + x0.x + b0, c[ms][ns][1] + x0.y + b1);
            *(float2*)(out + base1) = make_float2(c[ms][ns][2] + x1.x + b0, c[ms][ns][3] + x1.y + b1);
        }
}

extern "C" void kernel_launch(void* const* d_in, const int* in_sizes, int n_in,
                              void* d_out, int out_size) {
    const float* x      = (const float*)d_in[0];
    const float* dwc_w  = (const float*)d_in[1];
    const float* dwc_b  = (const float*)d_in[2];
    const float* upc_w  = (const float*)d_in[3];
    const float* upc_b  = (const float*)d_in[4];
    const float* few    = (const float*)d_in[5];
    const float* feb    = (const float*)d_in[6];
    const float* gaw    = (const float*)d_in[7];
    const float* gab    = (const float*)d_in[8];
    const float* cw     = (const float*)d_in[9];
    const float* abg    = (const float*)d_in[10];
    const float* abb    = (const float*)d_in[11];
    const float* pjw    = (const float*)d_in[12];
    const float* pjb    = (const float*)d_in[13];
    const float* pbg    = (const float*)d_in[14];
    const float* pbb    = (const float*)d_in[15];
    const float* qw     = (const float*)d_in[16];
    const float* qb     = (const float*)d_in[17];
    const float* kvw    = (const float*)d_in[18];
    const float* kvb    = (const float*)d_in[19];
    float* out = (float*)d_out;

    k_conv1A<<<4096, 256>>>(x, dwc_w);
    k_conv1B<<<2048, 256>>>(dwc_b);
    k_fea2q<<<128, 256>>>(few, feb, qw, qb);
    k_ga<<<1024, 256>>>(gaw, gab);
    k_cluster<<<dim3(8, 64), 256>>>(cw);
    k_cstat<<<64, 256>>>();
    k_cfin<<<4, 256>>>(abg, abb);
    k_smcent<<<128, 256>>>();
    k_proj<<<64, 256>>>(pjw, pjb);
    k_bnkv<<<128, 128>>>(pbg, pbb, kvw, kvb);
    k_attn<<<1024, 256>>>();
    k_conv2<<<4096, 256>>>(x, upc_w, upc_b, out);
}